// round 1
// baseline (speedup 1.0000x reference)
#include <cuda_runtime.h>
#include <cstdint>

// Problem constants
#define Bb   512
#define Tt   512
#define Ff   32
#define Hh   128
#define Ee   64
#define G1   (4*Hh)        // 512 gate columns, layer 1
#define G2   (4*Ee)        // 256 gate columns, layer 2
#define K1   (Hh+Ff)       // 160 (h then x)
#define K2   (Hh+Ee)       // 192 (h1 then h2)
#define BT   4             // batch rows per block
#define NB   (Bb/BT)       // 128 blocks (one wave)

#define NR1  64            // layer1: K-slices held in registers
#define NS1  (K1-NR1)      // 96 K-slices in smem
#define NR2  96            // layer2: K-slices in registers
#define NS2  (K2-NR2)      // 96 in smem

#define SM1_FLOATS (NS1*G1 + K1*BT + G1*BT)   // 49152 + 640 + 2048
#define SM2_FLOATS (NS2*G2 + K2*BT + G2*BT)   // 24576 + 768 + 1024
#define SM1_BYTES  (SM1_FLOATS*4)             // 207360
#define SM2_BYTES  (SM2_FLOATS*4)             // 105472

// Scratch: layer-1 output sequence, [T][B][H] fp32 (128 MB)
__device__ float g_seq1[(size_t)Tt*Bb*Hh];

__device__ __forceinline__ float sigm(float z) {
    // 1/(1+e^-z); saturates correctly at +-inf
    return __fdividef(1.0f, 1.0f + __expf(-z));
}
__device__ __forceinline__ float tanh_(float z) {
    // (e^{2z}-1)/(e^{2z}+1) = 1 - 2/(e^{2z}+1); saturates correctly
    float e = __expf(2.0f*z);
    return 1.0f - __fdividef(2.0f, e + 1.0f);
}

// ---------------------------------------------------------------------------
// Phase 1: layer-1 LSTM. 128 blocks x 512 threads, 1 gate-column per thread,
// 4 batch rows per block. Weights: 64 K-slices in regs + 96 in smem (fp32).
// Writes full hidden sequence to g_seq1.
// ---------------------------------------------------------------------------
__global__ void __launch_bounds__(512, 1)
lstm1_kernel(const float* __restrict__ x,
             const float* __restrict__ Wih, const float* __restrict__ Whh,
             const float* __restrict__ bih, const float* __restrict__ bhh)
{
    extern __shared__ float sm[];
    float* w_s = sm;                 // [NS1][G1]
    float* a_s = w_s + NS1*G1;       // [K1][BT]  (h rows 0..127, x rows 128..159)
    float* g_s = a_s + K1*BT;        // [G1][BT]

    const int tid = threadIdx.x;
    const int col = tid;             // gate column 0..511
    const int r0  = blockIdx.x * BT; // first batch row

    // Register weights: k = 0..NR1-1 (all < H so always W_hh)
    float wr[NR1];
#pragma unroll
    for (int k = 0; k < NR1; k++) wr[k] = Whh[col*Hh + k];

    // Smem weights: k = NR1..K1-1, [k][col] layout
    for (int k = NR1; k < K1; k++) {
        float v = (k < Hh) ? Whh[col*Hh + k] : Wih[col*Ff + (k - Hh)];
        w_s[(k - NR1)*G1 + col] = v;
    }
    const float bias = bih[col] + bhh[col];

    // zero h-part of a_s
    for (int i = tid; i < Hh*BT; i += blockDim.x) a_s[i] = 0.0f;

    float c0 = 0.f, c1 = 0.f, c2 = 0.f, c3 = 0.f;

    const int bb = tid >> 5, ffi = tid & 31;   // (batch, feature) for x loaders
    float xcur = 0.0f;
    if (tid < Hh) xcur = x[((r0 + bb)*Tt + 0)*Ff + ffi];
    __syncthreads();

    for (int t = 0; t < Tt; t++) {
        // commit prefetched x_t
        if (tid < Hh) a_s[(Hh + ffi)*BT + bb] = xcur;
        __syncthreads();
        // prefetch x_{t+1} (latency hides under gate compute)
        if (tid < Hh && t + 1 < Tt) xcur = x[((r0 + bb)*Tt + (t + 1))*Ff + ffi];

        float acc0 = bias, acc1 = bias, acc2 = bias, acc3 = bias;
        const float4* a4 = (const float4*)a_s;
#pragma unroll
        for (int k = 0; k < NR1; k++) {
            float4 av = a4[k];                  // broadcast LDS.128
            acc0 = fmaf(av.x, wr[k], acc0);
            acc1 = fmaf(av.y, wr[k], acc1);
            acc2 = fmaf(av.z, wr[k], acc2);
            acc3 = fmaf(av.w, wr[k], acc3);
        }
#pragma unroll 8
        for (int k = NR1; k < K1; k++) {
            float wv = w_s[(k - NR1)*G1 + col]; // conflict-free LDS.32
            float4 av = a4[k];
            acc0 = fmaf(av.x, wv, acc0);
            acc1 = fmaf(av.y, wv, acc1);
            acc2 = fmaf(av.z, wv, acc2);
            acc3 = fmaf(av.w, wv, acc3);
        }
        ((float4*)g_s)[col] = make_float4(acc0, acc1, acc2, acc3);
        __syncthreads();

        // cell update: thread j < 128 owns hidden unit j for all 4 batch rows
        if (tid < Hh) {
            const float4* g4 = (const float4*)g_s;
            float4 gi = g4[tid];
            float4 gf = g4[Hh + tid];
            float4 gg = g4[2*Hh + tid];
            float4 go = g4[3*Hh + tid];

            c0 = sigm(gf.x)*c0 + sigm(gi.x)*tanh_(gg.x);
            c1 = sigm(gf.y)*c1 + sigm(gi.y)*tanh_(gg.y);
            c2 = sigm(gf.z)*c2 + sigm(gi.z)*tanh_(gg.z);
            c3 = sigm(gf.w)*c3 + sigm(gi.w)*tanh_(gg.w);
            float h0 = sigm(go.x)*tanh_(c0);
            float h1 = sigm(go.y)*tanh_(c1);
            float h2 = sigm(go.z)*tanh_(c2);
            float h3 = sigm(go.w)*tanh_(c3);

            ((float4*)a_s)[tid] = make_float4(h0, h1, h2, h3);

            size_t base = ((size_t)t*Bb + r0)*Hh + tid;
            g_seq1[base         ] = h0;
            g_seq1[base +   Hh  ] = h1;
            g_seq1[base + 2*Hh  ] = h2;
            g_seq1[base + 3*Hh  ] = h3;
        }
        // loop-top STS (x-part) is disjoint from h-part; the loop-top barrier
        // orders the update writes before the next gate compute.
    }
}

// ---------------------------------------------------------------------------
// Phase 2: layer-2 LSTM over g_seq1. 128 blocks x 256 threads.
// Writes final hidden state to out [B][E].
// ---------------------------------------------------------------------------
__global__ void __launch_bounds__(256, 1)
lstm2_kernel(const float* __restrict__ Wih, const float* __restrict__ Whh,
             const float* __restrict__ bih, const float* __restrict__ bhh,
             float* __restrict__ out)
{
    extern __shared__ float sm[];
    float* w_s = sm;                 // [NS2][G2]
    float* a_s = w_s + NS2*G2;       // [K2][BT] (h1 rows 0..127, h2 rows 128..191)
    float* g_s = a_s + K2*BT;        // [G2][BT]

    const int tid = threadIdx.x;
    const int col = tid;             // 0..255
    const int r0  = blockIdx.x * BT;

    float wr[NR2];
#pragma unroll
    for (int k = 0; k < NR2; k++) wr[k] = Wih[col*Hh + k];   // NR2 <= H

    for (int k = NR2; k < K2; k++) {
        float v = (k < Hh) ? Wih[col*Hh + k] : Whh[col*Ee + (k - Hh)];
        w_s[(k - NR2)*G2 + col] = v;
    }
    const float bias = bih[col] + bhh[col];

    for (int i = tid; i < Ee*BT; i += blockDim.x) a_s[Hh*BT + i] = 0.0f;

    float c0 = 0.f, c1 = 0.f, c2 = 0.f, c3 = 0.f;
    float h0 = 0.f, h1 = 0.f, h2 = 0.f, h3 = 0.f;

    // each thread loads 2 seq1 values per step (coalesced)
    const int b1 = tid >> 7,       k1i = tid & 127;
    const int b2 = 2 + (tid >> 7), k2i = tid & 127;
    float v1 = g_seq1[((size_t)0*Bb + r0 + b1)*Hh + k1i];
    float v2 = g_seq1[((size_t)0*Bb + r0 + b2)*Hh + k2i];
    __syncthreads();

    for (int t = 0; t < Tt; t++) {
        a_s[k1i*BT + b1] = v1;
        a_s[k2i*BT + b2] = v2;
        __syncthreads();
        if (t + 1 < Tt) {
            v1 = g_seq1[((size_t)(t+1)*Bb + r0 + b1)*Hh + k1i];
            v2 = g_seq1[((size_t)(t+1)*Bb + r0 + b2)*Hh + k2i];
        }

        float acc0 = bias, acc1 = bias, acc2 = bias, acc3 = bias;
        const float4* a4 = (const float4*)a_s;
#pragma unroll
        for (int k = 0; k < NR2; k++) {
            float4 av = a4[k];
            acc0 = fmaf(av.x, wr[k], acc0);
            acc1 = fmaf(av.y, wr[k], acc1);
            acc2 = fmaf(av.z, wr[k], acc2);
            acc3 = fmaf(av.w, wr[k], acc3);
        }
#pragma unroll 8
        for (int k = NR2; k < K2; k++) {
            float wv = w_s[(k - NR2)*G2 + col];
            float4 av = a4[k];
            acc0 = fmaf(av.x, wv, acc0);
            acc1 = fmaf(av.y, wv, acc1);
            acc2 = fmaf(av.z, wv, acc2);
            acc3 = fmaf(av.w, wv, acc3);
        }
        ((float4*)g_s)[col] = make_float4(acc0, acc1, acc2, acc3);
        __syncthreads();

        if (tid < Ee) {
            const float4* g4 = (const float4*)g_s;
            float4 gi = g4[tid];
            float4 gf = g4[Ee + tid];
            float4 gg = g4[2*Ee + tid];
            float4 go = g4[3*Ee + tid];

            c0 = sigm(gf.x)*c0 + sigm(gi.x)*tanh_(gg.x);
            c1 = sigm(gf.y)*c1 + sigm(gi.y)*tanh_(gg.y);
            c2 = sigm(gf.z)*c2 + sigm(gi.z)*tanh_(gg.z);
            c3 = sigm(gf.w)*c3 + sigm(gi.w)*tanh_(gg.w);
            h0 = sigm(go.x)*tanh_(c0);
            h1 = sigm(go.y)*tanh_(c1);
            h2 = sigm(go.z)*tanh_(c2);
            h3 = sigm(go.w)*tanh_(c3);

            ((float4*)a_s)[Hh + tid] = make_float4(h0, h1, h2, h3);
        }
    }

    if (tid < Ee) {
        out[(r0 + 0)*Ee + tid] = h0;
        out[(r0 + 1)*Ee + tid] = h1;
        out[(r0 + 2)*Ee + tid] = h2;
        out[(r0 + 3)*Ee + tid] = h3;
    }
}

extern "C" void kernel_launch(void* const* d_in, const int* in_sizes, int n_in,
                              void* d_out, int out_size)
{
    const float* x    = (const float*)d_in[0];
    const float* Wih1 = (const float*)d_in[1];
    const float* Whh1 = (const float*)d_in[2];
    const float* bih1 = (const float*)d_in[3];
    const float* bhh1 = (const float*)d_in[4];
    const float* Wih2 = (const float*)d_in[5];
    const float* Whh2 = (const float*)d_in[6];
    const float* bih2 = (const float*)d_in[7];
    const float* bhh2 = (const float*)d_in[8];
    float* out = (float*)d_out;

    cudaFuncSetAttribute(lstm1_kernel, cudaFuncAttributeMaxDynamicSharedMemorySize, SM1_BYTES);
    cudaFuncSetAttribute(lstm2_kernel, cudaFuncAttributeMaxDynamicSharedMemorySize, SM2_BYTES);

    lstm1_kernel<<<NB, 512, SM1_BYTES>>>(x, Wih1, Whh1, bih1, bhh1);
    lstm2_kernel<<<NB, 256, SM2_BYTES>>>(Wih2, Whh2, bih2, bhh2, out);
}

// round 2
// speedup vs baseline: 1.0959x; 1.0959x over previous
#include <cuda_runtime.h>
#include <cstdint>

typedef unsigned long long u64;

// Problem constants
#define Bb   512
#define Tt   512
#define Ff   32
#define Hh   128
#define Ee   64
#define BT   4             // batch rows per block
#define NB   (Bb/BT)       // 128 blocks (one wave)

// Layer 1: 512 gate cols -> 256 col-pairs, K1=160 split in 2 halves of 80
#define P1R  36            // reg-resident packed weight slices per half
#define P1S  44            // smem packed weight slices per half (80-36)
#define WS1_BYTES (2*P1S*256*8)            // 180224
#define A2_1_BYTES (160*4*8)               // 5120
#define PF_1_BYTES (2*4*512*4)             // 16384
#define SM1_BYTES (WS1_BYTES + A2_1_BYTES + PF_1_BYTES)   // 201728

// Layer 2: 256 gate cols -> 128 col-pairs, K2=192 split in 4 quarters of 48
#define P2R  40
#define P2S  8
#define WS2_BYTES (4*P2S*128*8)            // 32768
#define A2_2_BYTES (192*4*8)               // 6144
#define PF_2_BYTES (4*4*256*4)             // 16384
#define SM2_BYTES (WS2_BYTES + A2_2_BYTES + PF_2_BYTES)   // 55296

// Scratch: layer-1 output sequence, [T][B][H] fp32
__device__ float g_seq1[(size_t)Tt*Bb*Hh];

__device__ __forceinline__ u64 ffma2(u64 a, u64 b, u64 c) {
    u64 d;
    asm("fma.rn.f32x2 %0, %1, %2, %3;" : "=l"(d) : "l"(a), "l"(b), "l"(c));
    return d;
}
__device__ __forceinline__ u64 pk2(float x, float y) {
    u64 r;
    asm("mov.b64 %0, {%1, %2};" : "=l"(r) : "f"(x), "f"(y));
    return r;
}
__device__ __forceinline__ float sigm(float z) {
    return __fdividef(1.0f, 1.0f + __expf(-z));
}
__device__ __forceinline__ float tanh_(float z) {
    float e = __expf(2.0f*z);
    return 1.0f - __fdividef(2.0f, e + 1.0f);
}

// ---------------------------------------------------------------------------
// Layer-1 LSTM. 128 blocks x 512 threads. thread = (col-pair cp, K-half).
// FFMA2 over batch via duplicated-activation smem; split-K partials in smem.
// ---------------------------------------------------------------------------
__global__ void __launch_bounds__(512, 1)
lstm1_kernel(const float* __restrict__ x,
             const float* __restrict__ Wih, const float* __restrict__ Whh,
             const float* __restrict__ bih, const float* __restrict__ bhh)
{
    extern __shared__ char smraw[];
    u64*   ws = (u64*)smraw;                               // [2*P1S][256] packed pairs
    u64*   a2 = (u64*)(smraw + WS1_BYTES);                 // [160][4] dup activations
    float* pf = (float*)(smraw + WS1_BYTES + A2_1_BYTES);  // [2][4][512] partials
    u64*   pu = (u64*)pf;

    const int tid  = threadIdx.x;
    const int cp   = tid & 255;
    const int half = tid >> 8;
    const int c0   = cp*2, c1 = c0 + 1;
    const int r0   = blockIdx.x * BT;
    const int k0   = half * 80;

    // packed weights: regs first P1R slices, rest in smem
    u64 wreg[P1R];
#pragma unroll
    for (int i = 0; i < P1R; i++) {
        int k = k0 + i;
        float w0 = (k < Hh) ? Whh[c0*Hh + k] : Wih[c0*Ff + (k - Hh)];
        float w1 = (k < Hh) ? Whh[c1*Hh + k] : Wih[c1*Ff + (k - Hh)];
        wreg[i] = pk2(w0, w1);
    }
    for (int i = P1R; i < 80; i++) {
        int k = k0 + i;
        float w0 = (k < Hh) ? Whh[c0*Hh + k] : Wih[c0*Ff + (k - Hh)];
        float w1 = (k < Hh) ? Whh[c1*Hh + k] : Wih[c1*Ff + (k - Hh)];
        ws[(half*P1S + (i - P1R))*256 + cp] = pk2(w0, w1);
    }
    u64 bp = 0ULL;
    if (half == 0) bp = pk2(bih[c0] + bhh[c0], bih[c1] + bhh[c1]);

    // zero h region of a2
    for (int i = tid; i < Hh*BT; i += 512) a2[i] = 0ULL;

    // x loaders: threads 0..127 own (feature xf, batch xb)
    const int xf = tid & 31, xb = (tid >> 5) & 3;
    float xc = 0.0f;
    if (tid < Hh) {
        float x0 = x[((size_t)(r0 + xb)*Tt + 0)*Ff + xf];
        a2[(Hh + xf)*4 + xb] = pk2(x0, x0);
        xc = x[((size_t)(r0 + xb)*Tt + 1)*Ff + xf];
    }
    const int ej = tid & 127, eb = tid >> 7;   // epilogue cell (hidden j, batch b)
    float cst = 0.0f;
    __syncthreads();

    const ulonglong2* a2v = (const ulonglong2*)(a2 + (size_t)k0*4);
    const u64* wsp = ws + (half*P1S)*256 + cp;

    for (int t = 0; t < Tt; t++) {
        u64 acc0 = bp, acc1 = bp, acc2 = bp, acc3 = bp;
#pragma unroll
        for (int i = 0; i < P1R; i++) {
            ulonglong2 vA = a2v[2*i];
            ulonglong2 vB = a2v[2*i + 1];
            acc0 = ffma2(wreg[i], vA.x, acc0);
            acc1 = ffma2(wreg[i], vA.y, acc1);
            acc2 = ffma2(wreg[i], vB.x, acc2);
            acc3 = ffma2(wreg[i], vB.y, acc3);
        }
#pragma unroll 4
        for (int i = P1R; i < 80; i++) {
            u64 w = wsp[(i - P1R)*256];
            ulonglong2 vA = a2v[2*i];
            ulonglong2 vB = a2v[2*i + 1];
            acc0 = ffma2(w, vA.x, acc0);
            acc1 = ffma2(w, vA.y, acc1);
            acc2 = ffma2(w, vB.x, acc2);
            acc3 = ffma2(w, vB.y, acc3);
        }
        pu[(half*4 + 0)*256 + cp] = acc0;
        pu[(half*4 + 1)*256 + cp] = acc1;
        pu[(half*4 + 2)*256 + cp] = acc2;
        pu[(half*4 + 3)*256 + cp] = acc3;
        __syncthreads();

        // epilogue: all 512 threads, one (j,b) cell each
        {
            const float* pb = pf + eb*512;
            float zi = pb[        ej] + pb[2048 +       ej];
            float zf = pb[128  +  ej] + pb[2048 + 128 + ej];
            float zg = pb[256  +  ej] + pb[2048 + 256 + ej];
            float zo = pb[384  +  ej] + pb[2048 + 384 + ej];
            cst = sigm(zf)*cst + sigm(zi)*tanh_(zg);
            float h = sigm(zo)*tanh_(cst);
            a2[ej*4 + eb] = pk2(h, h);
            g_seq1[((size_t)t*Bb + r0 + eb)*Hh + ej] = h;
            if (tid < Hh) {
                a2[(Hh + xf)*4 + xb] = pk2(xc, xc);
                xc = (t + 2 < Tt) ? x[((size_t)(r0 + xb)*Tt + t + 2)*Ff + xf] : 0.0f;
            }
        }
        __syncthreads();
    }
}

// ---------------------------------------------------------------------------
// Layer-2 LSTM. 128 blocks x 512 threads. thread = (col-pair cp, K-quarter q).
// All-but-8 weight pairs in registers; 4-way split-K.
// ---------------------------------------------------------------------------
__global__ void __launch_bounds__(512, 1)
lstm2_kernel(const float* __restrict__ Wih, const float* __restrict__ Whh,
             const float* __restrict__ bih, const float* __restrict__ bhh,
             float* __restrict__ out)
{
    extern __shared__ char smraw[];
    u64*   ws = (u64*)smraw;                               // [4*P2S][128]
    u64*   a2 = (u64*)(smraw + WS2_BYTES);                 // [192][4]
    float* pf = (float*)(smraw + WS2_BYTES + A2_2_BYTES);  // [4][4][256]
    u64*   pu = (u64*)pf;

    const int tid = threadIdx.x;
    const int cp  = tid & 127;
    const int q   = tid >> 7;
    const int c0  = cp*2, c1 = c0 + 1;
    const int r0  = blockIdx.x * BT;
    const int k0  = q * 48;

    u64 wreg[P2R];
#pragma unroll
    for (int i = 0; i < P2R; i++) {
        int k = k0 + i;
        float w0 = (k < Hh) ? Wih[c0*Hh + k] : Whh[c0*Ee + (k - Hh)];
        float w1 = (k < Hh) ? Wih[c1*Hh + k] : Whh[c1*Ee + (k - Hh)];
        wreg[i] = pk2(w0, w1);
    }
    for (int i = P2R; i < 48; i++) {
        int k = k0 + i;
        float w0 = (k < Hh) ? Wih[c0*Hh + k] : Whh[c0*Ee + (k - Hh)];
        float w1 = (k < Hh) ? Wih[c1*Hh + k] : Whh[c1*Ee + (k - Hh)];
        ws[(q*P2S + (i - P2R))*128 + cp] = pk2(w0, w1);
    }
    u64 bp = 0ULL;
    if (q == 0) bp = pk2(bih[c0] + bhh[c0], bih[c1] + bhh[c1]);

    // zero h2 region
    for (int i = tid; i < Ee*BT; i += 512) a2[Hh*4 + i] = 0ULL;

    // h1 loader mapping: kk = cp, bb = q (512 threads = 128 x 4 exactly)
    const int kk = cp, bb = q;
    float v = g_seq1[((size_t)0*Bb + r0 + bb)*Hh + kk];

    const int ej = tid & 63, eb = (tid >> 6) & 3;
    float cst = 0.0f, hout = 0.0f;

    const u64* wsp = ws + (q*P2S)*128 + cp;

    for (int t = 0; t < Tt; t++) {
        a2[kk*4 + bb] = pk2(v, v);
        __syncthreads();
        if (t + 1 < Tt) v = g_seq1[((size_t)(t+1)*Bb + r0 + bb)*Hh + kk];

        const ulonglong2* a2v = (const ulonglong2*)(a2 + (size_t)k0*4);
        u64 acc0 = bp, acc1 = bp, acc2 = bp, acc3 = bp;
#pragma unroll
        for (int i = 0; i < P2R; i++) {
            ulonglong2 vA = a2v[2*i];
            ulonglong2 vB = a2v[2*i + 1];
            acc0 = ffma2(wreg[i], vA.x, acc0);
            acc1 = ffma2(wreg[i], vA.y, acc1);
            acc2 = ffma2(wreg[i], vB.x, acc2);
            acc3 = ffma2(wreg[i], vB.y, acc3);
        }
#pragma unroll
        for (int i = P2R; i < 48; i++) {
            u64 w = wsp[(i - P2R)*128];
            ulonglong2 vA = a2v[2*i];
            ulonglong2 vB = a2v[2*i + 1];
            acc0 = ffma2(w, vA.x, acc0);
            acc1 = ffma2(w, vA.y, acc1);
            acc2 = ffma2(w, vB.x, acc2);
            acc3 = ffma2(w, vB.y, acc3);
        }
        pu[(q*4 + 0)*128 + cp] = acc0;
        pu[(q*4 + 1)*128 + cp] = acc1;
        pu[(q*4 + 2)*128 + cp] = acc2;
        pu[(q*4 + 3)*128 + cp] = acc3;
        __syncthreads();

        if (tid < 256) {
            const float* pb = pf + eb*256;
            float zi = pb[       ej] + pb[1024 +       ej] + pb[2048 +       ej] + pb[3072 +       ej];
            float zf = pb[ 64 +  ej] + pb[1024 +  64 + ej] + pb[2048 +  64 + ej] + pb[3072 +  64 + ej];
            float zg = pb[128 +  ej] + pb[1024 + 128 + ej] + pb[2048 + 128 + ej] + pb[3072 + 128 + ej];
            float zo = pb[192 +  ej] + pb[1024 + 192 + ej] + pb[2048 + 192 + ej] + pb[3072 + 192 + ej];
            cst = sigm(zf)*cst + sigm(zi)*tanh_(zg);
            hout = sigm(zo)*tanh_(cst);
            a2[(Hh + ej)*4 + eb] = pk2(hout, hout);
        }
        // next-iteration top commit writes a disjoint a2 region; the barrier at
        // loop top orders epilogue h2 writes before the next GEMV reads.
    }

    if (tid < 256) out[(size_t)(r0 + eb)*Ee + ej] = hout;
}

extern "C" void kernel_launch(void* const* d_in, const int* in_sizes, int n_in,
                              void* d_out, int out_size)
{
    const float* x    = (const float*)d_in[0];
    const float* Wih1 = (const float*)d_in[1];
    const float* Whh1 = (const float*)d_in[2];
    const float* bih1 = (const float*)d_in[3];
    const float* bhh1 = (const float*)d_in[4];
    const float* Wih2 = (const float*)d_in[5];
    const float* Whh2 = (const float*)d_in[6];
    const float* bih2 = (const float*)d_in[7];
    const float* bhh2 = (const float*)d_in[8];
    float* out = (float*)d_out;

    cudaFuncSetAttribute(lstm1_kernel, cudaFuncAttributeMaxDynamicSharedMemorySize, SM1_BYTES);
    cudaFuncSetAttribute(lstm2_kernel, cudaFuncAttributeMaxDynamicSharedMemorySize, SM2_BYTES);

    lstm1_kernel<<<NB, 512, SM1_BYTES>>>(x, Wih1, Whh1, bih1, bhh1);
    lstm2_kernel<<<NB, 512, SM2_BYTES>>>(Wih2, Whh2, bih2, bhh2, out);
}

// round 3
// speedup vs baseline: 1.0964x; 1.0004x over previous
#include <cuda_runtime.h>
#include <cstdint>

typedef unsigned long long u64;

// Problem constants
#define Bb   512
#define Tt   512
#define Ff   32
#define Hh   128
#define Ee   64
#define BT   4             // batch rows per block
#define NB   (Bb/BT)       // 128 blocks (one wave)

// Layer 1: 512 gate cols -> 256 col-pairs, K1=160 split in 2 halves of 80
#define P1R  36            // reg-resident packed weight slices per half
#define P1S  44            // smem packed weight slices per half (80-36)
#define WS1_BYTES (2*P1S*256*8)            // 180224
#define A2_1_BYTES (160*4*8)               // 5120
#define PF_1_BYTES (2*4*512*4)             // 16384
#define SM1_BYTES (WS1_BYTES + A2_1_BYTES + PF_1_BYTES)   // 201728

// Layer 2: 256 gate cols -> 128 col-pairs, K2=192 split in 4 quarters of 48
#define P2R  40
#define P2S  8
#define WS2_BYTES (4*P2S*128*8)            // 32768
#define A2_2_BYTES (192*4*8)               // 6144
#define PF_2_BYTES (4*4*256*4)             // 16384
#define SM2_BYTES (WS2_BYTES + A2_2_BYTES + PF_2_BYTES)   // 55296

// Scratch: layer-1 output sequence, [T][B][H] fp32
__device__ float g_seq1[(size_t)Tt*Bb*Hh];

__device__ __forceinline__ u64 ffma2(u64 a, u64 b, u64 c) {
    u64 d;
    asm("fma.rn.f32x2 %0, %1, %2, %3;" : "=l"(d) : "l"(a), "l"(b), "l"(c));
    return d;
}
__device__ __forceinline__ u64 pk2(float x, float y) {
    u64 r;
    asm("mov.b64 %0, {%1, %2};" : "=l"(r) : "f"(x), "f"(y));
    return r;
}
__device__ __forceinline__ float sigm(float z) {
    return __fdividef(1.0f, 1.0f + __expf(-z));
}
__device__ __forceinline__ float tanh_(float z) {
    float e = __expf(2.0f*z);
    return 1.0f - __fdividef(2.0f, e + 1.0f);
}

// ---------------------------------------------------------------------------
// Layer-1 LSTM. 128 blocks x 512 threads. thread = (col-pair cp, K-half).
// FFMA2 over batch via duplicated-activation smem; split-K partials in smem.
// ---------------------------------------------------------------------------
__global__ void __launch_bounds__(512, 1)
lstm1_kernel(const float* __restrict__ x,
             const float* __restrict__ Wih, const float* __restrict__ Whh,
             const float* __restrict__ bih, const float* __restrict__ bhh)
{
    extern __shared__ char smraw[];
    u64*   ws = (u64*)smraw;                               // [2*P1S][256] packed pairs
    u64*   a2 = (u64*)(smraw + WS1_BYTES);                 // [160][4] dup activations
    float* pf = (float*)(smraw + WS1_BYTES + A2_1_BYTES);  // [2][4][512] partials
    u64*   pu = (u64*)pf;

    const int tid  = threadIdx.x;
    const int cp   = tid & 255;
    const int half = tid >> 8;
    const int c0   = cp*2, c1 = c0 + 1;
    const int r0   = blockIdx.x * BT;
    const int k0   = half * 80;

    // packed weights: regs first P1R slices, rest in smem
    u64 wreg[P1R];
#pragma unroll
    for (int i = 0; i < P1R; i++) {
        int k = k0 + i;
        float w0 = (k < Hh) ? Whh[c0*Hh + k] : Wih[c0*Ff + (k - Hh)];
        float w1 = (k < Hh) ? Whh[c1*Hh + k] : Wih[c1*Ff + (k - Hh)];
        wreg[i] = pk2(w0, w1);
    }
    for (int i = P1R; i < 80; i++) {
        int k = k0 + i;
        float w0 = (k < Hh) ? Whh[c0*Hh + k] : Wih[c0*Ff + (k - Hh)];
        float w1 = (k < Hh) ? Whh[c1*Hh + k] : Wih[c1*Ff + (k - Hh)];
        ws[(half*P1S + (i - P1R))*256 + cp] = pk2(w0, w1);
    }
    u64 bp = 0ULL;
    if (half == 0) bp = pk2(bih[c0] + bhh[c0], bih[c1] + bhh[c1]);

    // zero h region of a2
    for (int i = tid; i < Hh*BT; i += 512) a2[i] = 0ULL;

    // x loaders: threads 0..127 own (feature xf, batch xb)
    const int xf = tid & 31, xb = (tid >> 5) & 3;
    float xc = 0.0f;
    if (tid < Hh) {
        float x0 = x[((size_t)(r0 + xb)*Tt + 0)*Ff + xf];
        a2[(Hh + xf)*4 + xb] = pk2(x0, x0);
        xc = x[((size_t)(r0 + xb)*Tt + 1)*Ff + xf];
    }
    const int ej = tid & 127, eb = tid >> 7;   // epilogue cell (hidden j, batch b)
    float cst = 0.0f;
    __syncthreads();

    const ulonglong2* a2v = (const ulonglong2*)(a2 + (size_t)k0*4);
    const u64* wsp = ws + (half*P1S)*256 + cp;

    for (int t = 0; t < Tt; t++) {
        u64 acc0 = bp, acc1 = bp, acc2 = bp, acc3 = bp;
#pragma unroll
        for (int i = 0; i < P1R; i++) {
            ulonglong2 vA = a2v[2*i];
            ulonglong2 vB = a2v[2*i + 1];
            acc0 = ffma2(wreg[i], vA.x, acc0);
            acc1 = ffma2(wreg[i], vA.y, acc1);
            acc2 = ffma2(wreg[i], vB.x, acc2);
            acc3 = ffma2(wreg[i], vB.y, acc3);
        }
#pragma unroll 4
        for (int i = P1R; i < 80; i++) {
            u64 w = wsp[(i - P1R)*256];
            ulonglong2 vA = a2v[2*i];
            ulonglong2 vB = a2v[2*i + 1];
            acc0 = ffma2(w, vA.x, acc0);
            acc1 = ffma2(w, vA.y, acc1);
            acc2 = ffma2(w, vB.x, acc2);
            acc3 = ffma2(w, vB.y, acc3);
        }
        pu[(half*4 + 0)*256 + cp] = acc0;
        pu[(half*4 + 1)*256 + cp] = acc1;
        pu[(half*4 + 2)*256 + cp] = acc2;
        pu[(half*4 + 3)*256 + cp] = acc3;
        __syncthreads();

        // epilogue: all 512 threads, one (j,b) cell each
        {
            const float* pb = pf + eb*512;
            float zi = pb[        ej] + pb[2048 +       ej];
            float zf = pb[128  +  ej] + pb[2048 + 128 + ej];
            float zg = pb[256  +  ej] + pb[2048 + 256 + ej];
            float zo = pb[384  +  ej] + pb[2048 + 384 + ej];
            cst = sigm(zf)*cst + sigm(zi)*tanh_(zg);
            float h = sigm(zo)*tanh_(cst);
            a2[ej*4 + eb] = pk2(h, h);
            g_seq1[((size_t)t*Bb + r0 + eb)*Hh + ej] = h;
            if (tid < Hh) {
                a2[(Hh + xf)*4 + xb] = pk2(xc, xc);
                xc = (t + 2 < Tt) ? x[((size_t)(r0 + xb)*Tt + t + 2)*Ff + xf] : 0.0f;
            }
        }
        __syncthreads();
    }
}

// ---------------------------------------------------------------------------
// Layer-2 LSTM. 128 blocks x 512 threads. thread = (col-pair cp, K-quarter q).
// All-but-8 weight pairs in registers; 4-way split-K.
// ---------------------------------------------------------------------------
__global__ void __launch_bounds__(512, 1)
lstm2_kernel(const float* __restrict__ Wih, const float* __restrict__ Whh,
             const float* __restrict__ bih, const float* __restrict__ bhh,
             float* __restrict__ out)
{
    extern __shared__ char smraw[];
    u64*   ws = (u64*)smraw;                               // [4*P2S][128]
    u64*   a2 = (u64*)(smraw + WS2_BYTES);                 // [192][4]
    float* pf = (float*)(smraw + WS2_BYTES + A2_2_BYTES);  // [4][4][256]
    u64*   pu = (u64*)pf;

    const int tid = threadIdx.x;
    const int cp  = tid & 127;
    const int q   = tid >> 7;
    const int c0  = cp*2, c1 = c0 + 1;
    const int r0  = blockIdx.x * BT;
    const int k0  = q * 48;

    u64 wreg[P2R];
#pragma unroll
    for (int i = 0; i < P2R; i++) {
        int k = k0 + i;
        float w0 = (k < Hh) ? Wih[c0*Hh + k] : Whh[c0*Ee + (k - Hh)];
        float w1 = (k < Hh) ? Wih[c1*Hh + k] : Whh[c1*Ee + (k - Hh)];
        wreg[i] = pk2(w0, w1);
    }
    for (int i = P2R; i < 48; i++) {
        int k = k0 + i;
        float w0 = (k < Hh) ? Wih[c0*Hh + k] : Whh[c0*Ee + (k - Hh)];
        float w1 = (k < Hh) ? Wih[c1*Hh + k] : Whh[c1*Ee + (k - Hh)];
        ws[(q*P2S + (i - P2R))*128 + cp] = pk2(w0, w1);
    }
    u64 bp = 0ULL;
    if (q == 0) bp = pk2(bih[c0] + bhh[c0], bih[c1] + bhh[c1]);

    // zero h2 region
    for (int i = tid; i < Ee*BT; i += 512) a2[Hh*4 + i] = 0ULL;

    // h1 loader mapping: kk = cp, bb = q (512 threads = 128 x 4 exactly)
    const int kk = cp, bb = q;
    float v = g_seq1[((size_t)0*Bb + r0 + bb)*Hh + kk];

    const int ej = tid & 63, eb = (tid >> 6) & 3;
    float cst = 0.0f, hout = 0.0f;

    const u64* wsp = ws + (q*P2S)*128 + cp;

    for (int t = 0; t < Tt; t++) {
        a2[kk*4 + bb] = pk2(v, v);
        __syncthreads();
        if (t + 1 < Tt) v = g_seq1[((size_t)(t+1)*Bb + r0 + bb)*Hh + kk];

        const ulonglong2* a2v = (const ulonglong2*)(a2 + (size_t)k0*4);
        u64 acc0 = bp, acc1 = bp, acc2 = bp, acc3 = bp;
#pragma unroll
        for (int i = 0; i < P2R; i++) {
            ulonglong2 vA = a2v[2*i];
            ulonglong2 vB = a2v[2*i + 1];
            acc0 = ffma2(wreg[i], vA.x, acc0);
            acc1 = ffma2(wreg[i], vA.y, acc1);
            acc2 = ffma2(wreg[i], vB.x, acc2);
            acc3 = ffma2(wreg[i], vB.y, acc3);
        }
#pragma unroll
        for (int i = P2R; i < 48; i++) {
            u64 w = wsp[(i - P2R)*128];
            ulonglong2 vA = a2v[2*i];
            ulonglong2 vB = a2v[2*i + 1];
            acc0 = ffma2(w, vA.x, acc0);
            acc1 = ffma2(w, vA.y, acc1);
            acc2 = ffma2(w, vB.x, acc2);
            acc3 = ffma2(w, vB.y, acc3);
        }
        pu[(q*4 + 0)*128 + cp] = acc0;
        pu[(q*4 + 1)*128 + cp] = acc1;
        pu[(q*4 + 2)*128 + cp] = acc2;
        pu[(q*4 + 3)*128 + cp] = acc3;
        __syncthreads();

        if (tid < 256) {
            const float* pb = pf + eb*256;
            float zi = pb[       ej] + pb[1024 +       ej] + pb[2048 +       ej] + pb[3072 +       ej];
            float zf = pb[ 64 +  ej] + pb[1024 +  64 + ej] + pb[2048 +  64 + ej] + pb[3072 +  64 + ej];
            float zg = pb[128 +  ej] + pb[1024 + 128 + ej] + pb[2048 + 128 + ej] + pb[3072 + 128 + ej];
            float zo = pb[192 +  ej] + pb[1024 + 192 + ej] + pb[2048 + 192 + ej] + pb[3072 + 192 + ej];
            cst = sigm(zf)*cst + sigm(zi)*tanh_(zg);
            hout = sigm(zo)*tanh_(cst);
            a2[(Hh + ej)*4 + eb] = pk2(hout, hout);
        }
        // next-iteration top commit writes a disjoint a2 region; the barrier at
        // loop top orders epilogue h2 writes before the next GEMV reads.
    }

    if (tid < 256) out[(size_t)(r0 + eb)*Ee + ej] = hout;
}

extern "C" void kernel_launch(void* const* d_in, const int* in_sizes, int n_in,
                              void* d_out, int out_size)
{
    const float* x    = (const float*)d_in[0];
    const float* Wih1 = (const float*)d_in[1];
    const float* Whh1 = (const float*)d_in[2];
    const float* bih1 = (const float*)d_in[3];
    const float* bhh1 = (const float*)d_in[4];
    const float* Wih2 = (const float*)d_in[5];
    const float* Whh2 = (const float*)d_in[6];
    const float* bih2 = (const float*)d_in[7];
    const float* bhh2 = (const float*)d_in[8];
    float* out = (float*)d_out;

    cudaFuncSetAttribute(lstm1_kernel, cudaFuncAttributeMaxDynamicSharedMemorySize, SM1_BYTES);
    cudaFuncSetAttribute(lstm2_kernel, cudaFuncAttributeMaxDynamicSharedMemorySize, SM2_BYTES);

    lstm1_kernel<<<NB, 512, SM1_BYTES>>>(x, Wih1, Whh1, bih1, bhh1);
    lstm2_kernel<<<NB, 512, SM2_BYTES>>>(Wih2, Whh2, bih2, bhh2, out);
}

// round 4
// speedup vs baseline: 1.0975x; 1.0011x over previous
#include <cuda_runtime.h>
#include <cstdint>

typedef unsigned long long u64;

// Problem constants
#define Bb   512
#define Tt   512
#define Ff   32
#define Hh   128
#define Ee   64
#define BT   4             // batch rows per block
#define NB   (Bb/BT)       // 128 blocks (one wave)

// Layer 1: 512 gate cols -> 256 col-pairs, K1=160 split in 2 halves of 80
#define P1R  36            // reg-resident packed weight slices per half
#define P1S  44            // smem packed weight slices per half (80-36)
#define WS1_BYTES (2*P1S*256*8)            // 180224
#define A2_1_BYTES (160*4*8)               // 5120
#define PF_1_BYTES (2*4*512*4)             // 16384
#define SM1_BYTES (WS1_BYTES + A2_1_BYTES + PF_1_BYTES)   // 201728

// Layer 2: 256 gate cols -> 128 col-pairs, K2=192 split in 4 quarters of 48
#define P2R  40
#define P2S  8
#define WS2_BYTES (4*P2S*128*8)            // 32768
#define A2_2_BYTES (192*4*8)               // 6144
#define PF_2_BYTES (4*4*256*4)             // 16384
#define SM2_BYTES (WS2_BYTES + A2_2_BYTES + PF_2_BYTES)   // 55296

// Scratch: layer-1 output sequence, [T][B][H] fp32
__device__ float g_seq1[(size_t)Tt*Bb*Hh];

__device__ __forceinline__ u64 ffma2(u64 a, u64 b, u64 c) {
    u64 d;
    asm("fma.rn.f32x2 %0, %1, %2, %3;" : "=l"(d) : "l"(a), "l"(b), "l"(c));
    return d;
}
__device__ __forceinline__ u64 pk2(float x, float y) {
    u64 r;
    asm("mov.b64 %0, {%1, %2};" : "=l"(r) : "f"(x), "f"(y));
    return r;
}
__device__ __forceinline__ float sigm(float z) {
    return __fdividef(1.0f, 1.0f + __expf(-z));
}
__device__ __forceinline__ float tanh_(float z) {
    float e = __expf(2.0f*z);
    return 1.0f - __fdividef(2.0f, e + 1.0f);
}

// ---------------------------------------------------------------------------
// Layer-1 LSTM. 128 blocks x 512 threads. thread = (col-pair cp, K-half).
// FFMA2 over batch via duplicated-activation smem; split-K partials in smem.
// ---------------------------------------------------------------------------
__global__ void __launch_bounds__(512, 1)
lstm1_kernel(const float* __restrict__ x,
             const float* __restrict__ Wih, const float* __restrict__ Whh,
             const float* __restrict__ bih, const float* __restrict__ bhh)
{
    extern __shared__ char smraw[];
    u64*   ws = (u64*)smraw;                               // [2*P1S][256] packed pairs
    u64*   a2 = (u64*)(smraw + WS1_BYTES);                 // [160][4] dup activations
    float* pf = (float*)(smraw + WS1_BYTES + A2_1_BYTES);  // [2][4][512] partials
    u64*   pu = (u64*)pf;

    const int tid  = threadIdx.x;
    const int cp   = tid & 255;
    const int half = tid >> 8;
    const int c0   = cp*2, c1 = c0 + 1;
    const int r0   = blockIdx.x * BT;
    const int k0   = half * 80;

    // packed weights: regs first P1R slices, rest in smem
    u64 wreg[P1R];
#pragma unroll
    for (int i = 0; i < P1R; i++) {
        int k = k0 + i;
        float w0 = (k < Hh) ? Whh[c0*Hh + k] : Wih[c0*Ff + (k - Hh)];
        float w1 = (k < Hh) ? Whh[c1*Hh + k] : Wih[c1*Ff + (k - Hh)];
        wreg[i] = pk2(w0, w1);
    }
    for (int i = P1R; i < 80; i++) {
        int k = k0 + i;
        float w0 = (k < Hh) ? Whh[c0*Hh + k] : Wih[c0*Ff + (k - Hh)];
        float w1 = (k < Hh) ? Whh[c1*Hh + k] : Wih[c1*Ff + (k - Hh)];
        ws[(half*P1S + (i - P1R))*256 + cp] = pk2(w0, w1);
    }
    u64 bp = 0ULL;
    if (half == 0) bp = pk2(bih[c0] + bhh[c0], bih[c1] + bhh[c1]);

    // zero h region of a2
    for (int i = tid; i < Hh*BT; i += 512) a2[i] = 0ULL;

    // x loaders: threads 0..127 own (feature xf, batch xb)
    const int xf = tid & 31, xb = (tid >> 5) & 3;
    float xc = 0.0f;
    if (tid < Hh) {
        float x0 = x[((size_t)(r0 + xb)*Tt + 0)*Ff + xf];
        a2[(Hh + xf)*4 + xb] = pk2(x0, x0);
        xc = x[((size_t)(r0 + xb)*Tt + 1)*Ff + xf];
    }
    const int ej = tid & 127, eb = tid >> 7;   // epilogue cell (hidden j, batch b)
    float cst = 0.0f;
    __syncthreads();

    const ulonglong2* a2v = (const ulonglong2*)(a2 + (size_t)k0*4);
    const u64* wsp = ws + (half*P1S)*256 + cp;

    for (int t = 0; t < Tt; t++) {
        u64 acc0 = bp, acc1 = bp, acc2 = bp, acc3 = bp;
#pragma unroll
        for (int i = 0; i < P1R; i++) {
            ulonglong2 vA = a2v[2*i];
            ulonglong2 vB = a2v[2*i + 1];
            acc0 = ffma2(wreg[i], vA.x, acc0);
            acc1 = ffma2(wreg[i], vA.y, acc1);
            acc2 = ffma2(wreg[i], vB.x, acc2);
            acc3 = ffma2(wreg[i], vB.y, acc3);
        }
#pragma unroll 4
        for (int i = P1R; i < 80; i++) {
            u64 w = wsp[(i - P1R)*256];
            ulonglong2 vA = a2v[2*i];
            ulonglong2 vB = a2v[2*i + 1];
            acc0 = ffma2(w, vA.x, acc0);
            acc1 = ffma2(w, vA.y, acc1);
            acc2 = ffma2(w, vB.x, acc2);
            acc3 = ffma2(w, vB.y, acc3);
        }
        pu[(half*4 + 0)*256 + cp] = acc0;
        pu[(half*4 + 1)*256 + cp] = acc1;
        pu[(half*4 + 2)*256 + cp] = acc2;
        pu[(half*4 + 3)*256 + cp] = acc3;
        __syncthreads();

        // epilogue: all 512 threads, one (j,b) cell each
        {
            const float* pb = pf + eb*512;
            float zi = pb[        ej] + pb[2048 +       ej];
            float zf = pb[128  +  ej] + pb[2048 + 128 + ej];
            float zg = pb[256  +  ej] + pb[2048 + 256 + ej];
            float zo = pb[384  +  ej] + pb[2048 + 384 + ej];
            cst = sigm(zf)*cst + sigm(zi)*tanh_(zg);
            float h = sigm(zo)*tanh_(cst);
            a2[ej*4 + eb] = pk2(h, h);
            g_seq1[((size_t)t*Bb + r0 + eb)*Hh + ej] = h;
            if (tid < Hh) {
                a2[(Hh + xf)*4 + xb] = pk2(xc, xc);
                xc = (t + 2 < Tt) ? x[((size_t)(r0 + xb)*Tt + t + 2)*Ff + xf] : 0.0f;
            }
        }
        __syncthreads();
    }
}

// ---------------------------------------------------------------------------
// Layer-2 LSTM. 128 blocks x 512 threads. thread = (col-pair cp, K-quarter q).
// All-but-8 weight pairs in registers; 4-way split-K.
// ---------------------------------------------------------------------------
__global__ void __launch_bounds__(512, 1)
lstm2_kernel(const float* __restrict__ Wih, const float* __restrict__ Whh,
             const float* __restrict__ bih, const float* __restrict__ bhh,
             float* __restrict__ out)
{
    extern __shared__ char smraw[];
    u64*   ws = (u64*)smraw;                               // [4*P2S][128]
    u64*   a2 = (u64*)(smraw + WS2_BYTES);                 // [192][4]
    float* pf = (float*)(smraw + WS2_BYTES + A2_2_BYTES);  // [4][4][256]
    u64*   pu = (u64*)pf;

    const int tid = threadIdx.x;
    const int cp  = tid & 127;
    const int q   = tid >> 7;
    const int c0  = cp*2, c1 = c0 + 1;
    const int r0  = blockIdx.x * BT;
    const int k0  = q * 48;

    u64 wreg[P2R];
#pragma unroll
    for (int i = 0; i < P2R; i++) {
        int k = k0 + i;
        float w0 = (k < Hh) ? Wih[c0*Hh + k] : Whh[c0*Ee + (k - Hh)];
        float w1 = (k < Hh) ? Wih[c1*Hh + k] : Whh[c1*Ee + (k - Hh)];
        wreg[i] = pk2(w0, w1);
    }
    for (int i = P2R; i < 48; i++) {
        int k = k0 + i;
        float w0 = (k < Hh) ? Wih[c0*Hh + k] : Whh[c0*Ee + (k - Hh)];
        float w1 = (k < Hh) ? Wih[c1*Hh + k] : Whh[c1*Ee + (k - Hh)];
        ws[(q*P2S + (i - P2R))*128 + cp] = pk2(w0, w1);
    }
    u64 bp = 0ULL;
    if (q == 0) bp = pk2(bih[c0] + bhh[c0], bih[c1] + bhh[c1]);

    // zero h2 region
    for (int i = tid; i < Ee*BT; i += 512) a2[Hh*4 + i] = 0ULL;

    // h1 loader mapping: kk = cp, bb = q (512 threads = 128 x 4 exactly)
    const int kk = cp, bb = q;
    float v = g_seq1[((size_t)0*Bb + r0 + bb)*Hh + kk];

    const int ej = tid & 63, eb = (tid >> 6) & 3;
    float cst = 0.0f, hout = 0.0f;

    const u64* wsp = ws + (q*P2S)*128 + cp;

    for (int t = 0; t < Tt; t++) {
        a2[kk*4 + bb] = pk2(v, v);
        __syncthreads();
        if (t + 1 < Tt) v = g_seq1[((size_t)(t+1)*Bb + r0 + bb)*Hh + kk];

        const ulonglong2* a2v = (const ulonglong2*)(a2 + (size_t)k0*4);
        u64 acc0 = bp, acc1 = bp, acc2 = bp, acc3 = bp;
#pragma unroll
        for (int i = 0; i < P2R; i++) {
            ulonglong2 vA = a2v[2*i];
            ulonglong2 vB = a2v[2*i + 1];
            acc0 = ffma2(wreg[i], vA.x, acc0);
            acc1 = ffma2(wreg[i], vA.y, acc1);
            acc2 = ffma2(wreg[i], vB.x, acc2);
            acc3 = ffma2(wreg[i], vB.y, acc3);
        }
#pragma unroll
        for (int i = P2R; i < 48; i++) {
            u64 w = wsp[(i - P2R)*128];
            ulonglong2 vA = a2v[2*i];
            ulonglong2 vB = a2v[2*i + 1];
            acc0 = ffma2(w, vA.x, acc0);
            acc1 = ffma2(w, vA.y, acc1);
            acc2 = ffma2(w, vB.x, acc2);
            acc3 = ffma2(w, vB.y, acc3);
        }
        pu[(q*4 + 0)*128 + cp] = acc0;
        pu[(q*4 + 1)*128 + cp] = acc1;
        pu[(q*4 + 2)*128 + cp] = acc2;
        pu[(q*4 + 3)*128 + cp] = acc3;
        __syncthreads();

        if (tid < 256) {
            const float* pb = pf + eb*256;
            float zi = pb[       ej] + pb[1024 +       ej] + pb[2048 +       ej] + pb[3072 +       ej];
            float zf = pb[ 64 +  ej] + pb[1024 +  64 + ej] + pb[2048 +  64 + ej] + pb[3072 +  64 + ej];
            float zg = pb[128 +  ej] + pb[1024 + 128 + ej] + pb[2048 + 128 + ej] + pb[3072 + 128 + ej];
            float zo = pb[192 +  ej] + pb[1024 + 192 + ej] + pb[2048 + 192 + ej] + pb[3072 + 192 + ej];
            cst = sigm(zf)*cst + sigm(zi)*tanh_(zg);
            hout = sigm(zo)*tanh_(cst);
            a2[(Hh + ej)*4 + eb] = pk2(hout, hout);
        }
        // next-iteration top commit writes a disjoint a2 region; the barrier at
        // loop top orders epilogue h2 writes before the next GEMV reads.
    }

    if (tid < 256) out[(size_t)(r0 + eb)*Ee + ej] = hout;
}

extern "C" void kernel_launch(void* const* d_in, const int* in_sizes, int n_in,
                              void* d_out, int out_size)
{
    const float* x    = (const float*)d_in[0];
    const float* Wih1 = (const float*)d_in[1];
    const float* Whh1 = (const float*)d_in[2];
    const float* bih1 = (const float*)d_in[3];
    const float* bhh1 = (const float*)d_in[4];
    const float* Wih2 = (const float*)d_in[5];
    const float* Whh2 = (const float*)d_in[6];
    const float* bih2 = (const float*)d_in[7];
    const float* bhh2 = (const float*)d_in[8];
    float* out = (float*)d_out;

    cudaFuncSetAttribute(lstm1_kernel, cudaFuncAttributeMaxDynamicSharedMemorySize, SM1_BYTES);
    cudaFuncSetAttribute(lstm2_kernel, cudaFuncAttributeMaxDynamicSharedMemorySize, SM2_BYTES);

    lstm1_kernel<<<NB, 512, SM1_BYTES>>>(x, Wih1, Whh1, bih1, bhh1);
    lstm2_kernel<<<NB, 512, SM2_BYTES>>>(Wih2, Whh2, bih2, bhh2, out);
}